// round 1
// baseline (speedup 1.0000x reference)
#include <cuda_runtime.h>
#include <cstdint>

#define BB 16
#define NN 2048
#define MM 2048
#define DD 128

// Scratch for row/col squared norms (allocation-free rule: __device__ globals)
__device__ __align__(16) float g_Qsq[BB * NN];
__device__ __align__(16) float g_KVsq[BB * MM];

// ---------------------------------------------------------------------------
// ||q||^2 per row of Q [B, N, D]: one warp per row, lane loads one float4.
// ---------------------------------------------------------------------------
__global__ void rowsq_kernel(const float* __restrict__ Q) {
    int row  = blockIdx.x * 8 + (threadIdx.x >> 5);   // 8 warps/block
    int lane = threadIdx.x & 31;
    const float4* p = reinterpret_cast<const float4*>(Q + (size_t)row * DD);
    float4 v = p[lane];                                // 32 lanes * 4 = 128
    float s = v.x * v.x + v.y * v.y + v.z * v.z + v.w * v.w;
#pragma unroll
    for (int o = 16; o > 0; o >>= 1) s += __shfl_xor_sync(0xffffffffu, s, o);
    if (lane == 0) g_Qsq[row] = s;
}

// ---------------------------------------------------------------------------
// ||k||^2 per column of KV [B, D, M]: thread per (b, m), strided-coalesced.
// ---------------------------------------------------------------------------
__global__ void colsq_kernel(const float* __restrict__ KV) {
    int idx = blockIdx.x * 256 + threadIdx.x;          // over B*M
    int b = idx >> 11;                                 // M = 2048 = 2^11
    int m = idx & (MM - 1);
    const float* p = KV + (size_t)b * DD * MM + m;
    float s = 0.f;
#pragma unroll 16
    for (int d = 0; d < DD; d++) {
        float v = __ldg(p + (size_t)d * MM);
        s = fmaf(v, v, s);
    }
    g_KVsq[idx] = s;
}

// ---------------------------------------------------------------------------
// Main fused GEMM + Gaussian epilogue.
// 128x128 block tile, BK=8, double-buffered smem, 8x8 per-thread microtile.
// Accumulators packed as f32x2 pairs; inner product uses fma.rn.f32x2
// (2x fp32 throughput vs scalar FFMA on sm_103a).
// ---------------------------------------------------------------------------

union U2 {
    float4 f4;
    unsigned long long u[2];
};
union P2 {
    unsigned long long u;
    float f[2];
};

#define FMA2(d, a, b) \
    asm("fma.rn.f32x2 %0, %1, %2, %3;" : "=l"(d) : "l"(a), "l"(b), "l"(d))

__global__ __launch_bounds__(256, 2) void gauss_kernel(
    const float* __restrict__ Q, const float* __restrict__ KV,
    const float* __restrict__ LS, float* __restrict__ OUT)
{
    __shared__ float As[2][8][128];   // transposed: As[k][n]
    __shared__ float Bs[2][8][128];   // Bs[k][m]

    const int b  = blockIdx.z;
    const int n0 = blockIdx.y * 128;
    const int m0 = blockIdx.x * 128;

    const float* Ag = Q  + ((size_t)b * NN + n0) * DD;     // [128 rows, D cols]
    const float* Bg = KV + (size_t)b * DD * MM + m0;       // [D rows, 128 cols]

    const int tid  = threadIdx.x;
    const int arow = tid >> 1;            // 0..127
    const int acol = (tid & 1) * 4;       // 0 or 4 within BK=8
    const int brow = tid >> 5;            // 0..7
    const int bcol = (tid & 31) * 4;      // 0..124

    const int tx = tid & 15;              // m microtile index
    const int ty = tid >> 4;              // n microtile index

    unsigned long long acc[8][4];         // 8 rows x 4 f32x2 pairs (8 cols)
#pragma unroll
    for (int i = 0; i < 8; i++)
#pragma unroll
        for (int j = 0; j < 4; j++) acc[i][j] = 0ull;

    // Prologue: stage tile 0
    {
        float4 ar = *reinterpret_cast<const float4*>(Ag + (size_t)arow * DD + acol);
        float4 br = *reinterpret_cast<const float4*>(Bg + (size_t)brow * MM + bcol);
        As[0][acol + 0][arow] = ar.x;
        As[0][acol + 1][arow] = ar.y;
        As[0][acol + 2][arow] = ar.z;
        As[0][acol + 3][arow] = ar.w;
        *reinterpret_cast<float4*>(&Bs[0][brow][bcol]) = br;
    }
    __syncthreads();

    int cur = 0;
#pragma unroll 1
    for (int t = 0; t < DD / 8; t++) {
        float4 arn, brn;
        if (t < DD / 8 - 1) {
            arn = *reinterpret_cast<const float4*>(
                Ag + (size_t)arow * DD + (t + 1) * 8 + acol);
            brn = *reinterpret_cast<const float4*>(
                Bg + ((size_t)(t + 1) * 8 + brow) * MM + bcol);
        }

#pragma unroll
        for (int kk = 0; kk < 8; kk++) {
            float4 a0 = *reinterpret_cast<const float4*>(&As[cur][kk][ty * 8]);
            float4 a1 = *reinterpret_cast<const float4*>(&As[cur][kk][ty * 8 + 4]);
            U2 ub0, ub1;
            ub0.f4 = *reinterpret_cast<const float4*>(&Bs[cur][kk][tx * 8]);
            ub1.f4 = *reinterpret_cast<const float4*>(&Bs[cur][kk][tx * 8 + 4]);

            float av[8] = {a0.x, a0.y, a0.z, a0.w, a1.x, a1.y, a1.z, a1.w};
#pragma unroll
            for (int i = 0; i < 8; i++) {
                unsigned long long aa;
                asm("mov.b64 %0, {%1, %1};"
                    : "=l"(aa) : "r"(__float_as_uint(av[i])));
                FMA2(acc[i][0], aa, ub0.u[0]);
                FMA2(acc[i][1], aa, ub0.u[1]);
                FMA2(acc[i][2], aa, ub1.u[0]);
                FMA2(acc[i][3], aa, ub1.u[1]);
            }
        }

        if (t < DD / 8 - 1) {
            int nxt = cur ^ 1;
            As[nxt][acol + 0][arow] = arn.x;
            As[nxt][acol + 1][arow] = arn.y;
            As[nxt][acol + 2][arow] = arn.z;
            As[nxt][acol + 3][arow] = arn.w;
            *reinterpret_cast<float4*>(&Bs[nxt][brow][bcol]) = brn;
            __syncthreads();
            cur = nxt;
        }
    }

    // Epilogue: out = exp(c * (qsq + kvsq - 2*qk)),  c = -0.5 / exp(2*ls)
    const float ls  = LS[0];
    const float c   = -0.5f * __expf(-2.0f * ls);
    const float m2c = -2.0f * c;

    float4 q0 = *reinterpret_cast<const float4*>(&g_Qsq[(size_t)b * NN + n0 + ty * 8]);
    float4 q1 = *reinterpret_cast<const float4*>(&g_Qsq[(size_t)b * NN + n0 + ty * 8 + 4]);
    float4 k0 = *reinterpret_cast<const float4*>(&g_KVsq[(size_t)b * MM + m0 + tx * 8]);
    float4 k1 = *reinterpret_cast<const float4*>(&g_KVsq[(size_t)b * MM + m0 + tx * 8 + 4]);

    float cq[8] = {c * q0.x, c * q0.y, c * q0.z, c * q0.w,
                   c * q1.x, c * q1.y, c * q1.z, c * q1.w};
    float ck[8] = {c * k0.x, c * k0.y, c * k0.z, c * k0.w,
                   c * k1.x, c * k1.y, c * k1.z, c * k1.w};

#pragma unroll
    for (int i = 0; i < 8; i++) {
        float* orow = OUT + ((size_t)(b * NN + n0 + ty * 8 + i)) * MM + m0 + tx * 8;
        float v[8];
#pragma unroll
        for (int j2 = 0; j2 < 4; j2++) {
            P2 p; p.u = acc[i][j2];
            v[2 * j2 + 0] = __expf(fmaf(m2c, p.f[0], cq[i] + ck[2 * j2 + 0]));
            v[2 * j2 + 1] = __expf(fmaf(m2c, p.f[1], cq[i] + ck[2 * j2 + 1]));
        }
        float4 o0 = {v[0], v[1], v[2], v[3]};
        float4 o1 = {v[4], v[5], v[6], v[7]};
        *reinterpret_cast<float4*>(orow)     = o0;
        *reinterpret_cast<float4*>(orow + 4) = o1;
    }
}

// ---------------------------------------------------------------------------
extern "C" void kernel_launch(void* const* d_in, const int* in_sizes, int n_in,
                              void* d_out, int out_size) {
    const float* Q  = (const float*)d_in[0];
    const float* KV = (const float*)d_in[1];
    const float* LS = (const float*)d_in[2];
    float* OUT = (float*)d_out;

    rowsq_kernel<<<BB * NN / 8, 256>>>(Q);
    colsq_kernel<<<BB * MM / 256, 256>>>(KV);

    dim3 grid(MM / 128, NN / 128, BB);
    gauss_kernel<<<grid, 256>>>(Q, KV, LS, OUT);
}

// round 4
// speedup vs baseline: 2.1000x; 2.1000x over previous
#include <cuda_runtime.h>
#include <cuda_bf16.h>
#include <cstdint>

#define BB 16
#define NN 2048
#define MM 2048
#define DD 128

// ---------------- scratch (__device__ globals: allocation-free rule) --------
__device__ __align__(16) float g_Qsq[BB * NN];
__device__ __align__(16) float g_Ksq[BB * MM];
__device__ __align__(16) __nv_bfloat16 g_Qhi[(size_t)BB * NN * DD];
__device__ __align__(16) __nv_bfloat16 g_Qlo[(size_t)BB * NN * DD];
__device__ __align__(16) __nv_bfloat16 g_KThi[(size_t)BB * MM * DD];  // [b, m, d]
__device__ __align__(16) __nv_bfloat16 g_KTlo[(size_t)BB * MM * DD];

// ---------------- helpers ---------------------------------------------------
__device__ __forceinline__ uint32_t smem_u32(const void* p) {
    uint32_t a;
    asm("{ .reg .u64 t; cvta.to.shared.u64 t, %1; cvt.u32.u64 %0, t; }"
        : "=r"(a) : "l"(p));
    return a;
}
__device__ __forceinline__ void ldsm4(uint32_t* r, uint32_t addr) {
    asm volatile("ldmatrix.sync.aligned.m8n8.x4.shared.b16 {%0,%1,%2,%3}, [%4];"
                 : "=r"(r[0]), "=r"(r[1]), "=r"(r[2]), "=r"(r[3]) : "r"(addr));
}
__device__ __forceinline__ void mma16816(float* c, const uint32_t* a,
                                         const uint32_t* b) {
    asm volatile(
        "mma.sync.aligned.m16n8k16.row.col.f32.bf16.bf16.f32 "
        "{%0,%1,%2,%3}, {%4,%5,%6,%7}, {%8,%9}, {%0,%1,%2,%3};"
        : "+f"(c[0]), "+f"(c[1]), "+f"(c[2]), "+f"(c[3])
        : "r"(a[0]), "r"(a[1]), "r"(a[2]), "r"(a[3]), "r"(b[0]), "r"(b[1]));
}

// ---------------------------------------------------------------------------
// Prepass 1: Q[b,n,d] -> Qhi/Qlo bf16 (row-major) + ||q||^2. One warp per row.
// ---------------------------------------------------------------------------
__global__ void qprep(const float* __restrict__ Q) {
    int row  = blockIdx.x * 8 + (threadIdx.x >> 5);
    int lane = threadIdx.x & 31;
    float4 v = reinterpret_cast<const float4*>(Q + (size_t)row * DD)[lane];
    float f[4] = {v.x, v.y, v.z, v.w};
    float s = v.x * v.x + v.y * v.y + v.z * v.z + v.w * v.w;
    uint32_t ph[2], pl[2];
#pragma unroll
    for (int j = 0; j < 2; j++) {
        __nv_bfloat16 h0 = __float2bfloat16(f[2 * j]);
        __nv_bfloat16 h1 = __float2bfloat16(f[2 * j + 1]);
        __nv_bfloat16 l0 = __float2bfloat16(f[2 * j] - __bfloat162float(h0));
        __nv_bfloat16 l1 = __float2bfloat16(f[2 * j + 1] - __bfloat162float(h1));
        ph[j] = (uint32_t)__bfloat16_as_ushort(h0) | ((uint32_t)__bfloat16_as_ushort(h1) << 16);
        pl[j] = (uint32_t)__bfloat16_as_ushort(l0) | ((uint32_t)__bfloat16_as_ushort(l1) << 16);
    }
    reinterpret_cast<uint2*>(g_Qhi + (size_t)row * DD)[lane] = make_uint2(ph[0], ph[1]);
    reinterpret_cast<uint2*>(g_Qlo + (size_t)row * DD)[lane] = make_uint2(pl[0], pl[1]);
#pragma unroll
    for (int o = 16; o > 0; o >>= 1) s += __shfl_xor_sync(0xffffffffu, s, o);
    if (lane == 0) g_Qsq[row] = s;
}

// ---------------------------------------------------------------------------
// Prepass 2: KV[b,d,m] -> transpose+convert to KThi/KTlo [b,m,d] + ||k||^2.
// ---------------------------------------------------------------------------
__global__ void kvprep(const float* __restrict__ KV) {
    __shared__ float s[128][33];
    __shared__ float csq[256];
    int b  = blockIdx.y;
    int m0 = blockIdx.x * 32;
    int t  = threadIdx.x;
    int mi = t & 31, dg = t >> 5;
    const float* base = KV + (size_t)b * DD * MM + m0;
    float acc = 0.f;
#pragma unroll
    for (int i = 0; i < 16; i++) {
        int d = i * 8 + dg;
        float v = base[(size_t)d * MM + mi];
        s[d][mi] = v;
        acc = fmaf(v, v, acc);
    }
    csq[t] = acc;
    __syncthreads();
    if (t < 32) {
        float a2 = 0.f;
#pragma unroll
        for (int j = 0; j < 8; j++) a2 += csq[t + j * 32];
        g_Ksq[(size_t)b * MM + m0 + t] = a2;
    }
#pragma unroll
    for (int it = 0; it < 2; it++) {
        int idx = it * 256 + t;
        int m = idx >> 4, kc = idx & 15, d0 = kc * 8;
        uint32_t ph[4], pl[4];
#pragma unroll
        for (int j = 0; j < 4; j++) {
            float a = s[d0 + 2 * j][m];
            float c = s[d0 + 2 * j + 1][m];
            __nv_bfloat16 ha = __float2bfloat16(a), hc = __float2bfloat16(c);
            __nv_bfloat16 la = __float2bfloat16(a - __bfloat162float(ha));
            __nv_bfloat16 lc = __float2bfloat16(c - __bfloat162float(hc));
            ph[j] = (uint32_t)__bfloat16_as_ushort(ha) | ((uint32_t)__bfloat16_as_ushort(hc) << 16);
            pl[j] = (uint32_t)__bfloat16_as_ushort(la) | ((uint32_t)__bfloat16_as_ushort(lc) << 16);
        }
        size_t off = ((size_t)b * MM + m0 + m) * DD + d0;
        *reinterpret_cast<uint4*>(g_KThi + off) = make_uint4(ph[0], ph[1], ph[2], ph[3]);
        *reinterpret_cast<uint4*>(g_KTlo + off) = make_uint4(pl[0], pl[1], pl[2], pl[3]);
    }
}

// ---------------------------------------------------------------------------
// Main kernel: 128(n) x 64(m) tile per CTA via ldmatrix + mma.sync bf16,
// 3-pass hi/lo split, fp32 accumulate, fused exp epilogue.
// Smem tiles: row pitch 256B, 16B chunks swizzled by (kc ^ (row & 7)).
// ---------------------------------------------------------------------------
#define SM_AHI 0
#define SM_ALO 32768
#define SM_BHI 65536
#define SM_BLO 81920
#define SMEM_TOTAL 98304

__global__ void __launch_bounds__(256, 2)
gauss_mma(const float* __restrict__ LS, float* __restrict__ OUT) {
    extern __shared__ char smem[];
    const uint32_t sb = smem_u32(smem);
    const int t = threadIdx.x, wid = t >> 5, lane = t & 31;
    const int b = blockIdx.z, n0 = blockIdx.y * 128, m0 = blockIdx.x * 64;

    // ---- bulk load the 4 operand tiles into swizzled smem (fully static) ----
    {
        const __nv_bfloat16* sA = g_Qhi + ((size_t)b * NN + n0) * DD;
#pragma unroll
        for (int i = 0; i < 8; i++) {
            int idx = i * 256 + t;
            int row = idx >> 4, kc = idx & 15;
            uint4 v = *reinterpret_cast<const uint4*>(sA + (size_t)row * DD + kc * 8);
            *reinterpret_cast<uint4*>(
                smem + SM_AHI + row * 256 + ((kc ^ (row & 7)) << 4)) = v;
        }
        const __nv_bfloat16* sAl = g_Qlo + ((size_t)b * NN + n0) * DD;
#pragma unroll
        for (int i = 0; i < 8; i++) {
            int idx = i * 256 + t;
            int row = idx >> 4, kc = idx & 15;
            uint4 v = *reinterpret_cast<const uint4*>(sAl + (size_t)row * DD + kc * 8);
            *reinterpret_cast<uint4*>(
                smem + SM_ALO + row * 256 + ((kc ^ (row & 7)) << 4)) = v;
        }
        const __nv_bfloat16* sB = g_KThi + ((size_t)b * MM + m0) * DD;
#pragma unroll
        for (int i = 0; i < 4; i++) {
            int idx = i * 256 + t;
            int row = idx >> 4, kc = idx & 15;
            uint4 v = *reinterpret_cast<const uint4*>(sB + (size_t)row * DD + kc * 8);
            *reinterpret_cast<uint4*>(
                smem + SM_BHI + row * 256 + ((kc ^ (row & 7)) << 4)) = v;
        }
        const __nv_bfloat16* sBl = g_KTlo + ((size_t)b * MM + m0) * DD;
#pragma unroll
        for (int i = 0; i < 4; i++) {
            int idx = i * 256 + t;
            int row = idx >> 4, kc = idx & 15;
            uint4 v = *reinterpret_cast<const uint4*>(sBl + (size_t)row * DD + kc * 8);
            *reinterpret_cast<uint4*>(
                smem + SM_BLO + row * 256 + ((kc ^ (row & 7)) << 4)) = v;
        }
    }
    __syncthreads();

    // ---- fragment addressing ----
    const int warp_r = wid & 1;        // 0..1 (64 out-rows each)
    const int warp_c = wid >> 1;       // 0..3 (16 out-cols each)
    const int rmask = lane & 7;

    // A (Q) ldmatrix lanes: mat = lane>>3; row = base + (lane&7) + (mat&1)*8;
    //                        kchunk offset cA = mat>>1
    const int cA = lane >> 4;
    uint32_t arow_base[4];
#pragma unroll
    for (int rt = 0; rt < 4; rt++)
        arow_base[rt] = (uint32_t)((warp_r * 64 + rt * 16 + (lane & 7) +
                                    (((lane >> 3) & 1) << 3)) * 256);
    // B (KT) ldmatrix lanes: mat = lane>>3; row = base + (lane&7) + (mat>>1)*8;
    //                         kchunk offset cB = mat&1
    const int cB = (lane >> 3) & 1;
    const uint32_t brow_base =
        (uint32_t)((warp_c * 16 + (lane & 7) + ((lane >> 4) << 3)) * 256);

    float acc[4][2][4];
#pragma unroll
    for (int rt = 0; rt < 4; rt++)
#pragma unroll
        for (int ct = 0; ct < 2; ct++)
#pragma unroll
            for (int j = 0; j < 4; j++) acc[rt][ct][j] = 0.f;

    // ---- main MMA loop: 8 k-steps x (hi*hi + hi*lo + lo*hi) ----
#pragma unroll
    for (int ks = 0; ks < 8; ks++) {
        uint32_t ah[4][4], al[4][4], bh[4], bl[4];
        uint32_t aswz = (uint32_t)((((ks << 1) + cA) ^ rmask) << 4);
#pragma unroll
        for (int rt = 0; rt < 4; rt++) {
            ldsm4(ah[rt], sb + SM_AHI + arow_base[rt] + aswz);
            ldsm4(al[rt], sb + SM_ALO + arow_base[rt] + aswz);
        }
        uint32_t bswz = (uint32_t)((((ks << 1) + cB) ^ rmask) << 4);
        ldsm4(bh, sb + SM_BHI + brow_base + bswz);
        ldsm4(bl, sb + SM_BLO + brow_base + bswz);

#pragma unroll
        for (int rt = 0; rt < 4; rt++) {
#pragma unroll
            for (int ct = 0; ct < 2; ct++) {
                mma16816(acc[rt][ct], ah[rt], bh + 2 * ct);
                mma16816(acc[rt][ct], ah[rt], bl + 2 * ct);
                mma16816(acc[rt][ct], al[rt], bh + 2 * ct);
            }
        }
    }

    // ---- fused Gaussian epilogue ----
    const float cc  = -0.5f * __expf(-2.0f * LS[0]);
    const float m2c = -2.0f * cc;

    const int r_base = n0 + warp_r * 64;
    const int c_base = m0 + warp_c * 16;
    float cq[4][2], ck[2][2];
#pragma unroll
    for (int rt = 0; rt < 4; rt++)
#pragma unroll
        for (int h = 0; h < 2; h++)
            cq[rt][h] = cc * __ldg(&g_Qsq[(size_t)b * NN + r_base + rt * 16 +
                                          (lane >> 2) + h * 8]);
#pragma unroll
    for (int ct = 0; ct < 2; ct++)
#pragma unroll
        for (int j = 0; j < 2; j++)
            ck[ct][j] = cc * __ldg(&g_Ksq[(size_t)b * MM + c_base + ct * 8 +
                                          2 * (lane & 3) + j]);

#pragma unroll
    for (int rt = 0; rt < 4; rt++) {
#pragma unroll
        for (int ct = 0; ct < 2; ct++) {
#pragma unroll
            for (int h = 0; h < 2; h++) {
                int row = r_base + rt * 16 + (lane >> 2) + h * 8;
                int col = c_base + ct * 8 + 2 * (lane & 3);
                float2 o;
                o.x = __expf(fmaf(m2c, acc[rt][ct][2 * h + 0], cq[rt][h] + ck[ct][0]));
                o.y = __expf(fmaf(m2c, acc[rt][ct][2 * h + 1], cq[rt][h] + ck[ct][1]));
                *reinterpret_cast<float2*>(
                    OUT + ((size_t)b * NN + row) * MM + col) = o;
            }
        }
    }
}

// ---------------------------------------------------------------------------
extern "C" void kernel_launch(void* const* d_in, const int* in_sizes, int n_in,
                              void* d_out, int out_size) {
    const float* Q  = (const float*)d_in[0];
    const float* KV = (const float*)d_in[1];
    const float* LS = (const float*)d_in[2];
    float* OUT = (float*)d_out;

    cudaFuncSetAttribute(gauss_mma, cudaFuncAttributeMaxDynamicSharedMemorySize,
                         SMEM_TOTAL);

    qprep<<<BB * NN / 8, 256>>>(Q);
    kvprep<<<dim3(MM / 32, BB), 256>>>(KV);

    dim3 grid(MM / 64, NN / 128, BB);
    gauss_mma<<<grid, 256, SMEM_TOTAL>>>(LS, OUT);
}

// round 5
// speedup vs baseline: 4.1584x; 1.9802x over previous
#include <cuda_runtime.h>
#include <cuda_fp16.h>
#include <cstdint>

#define BB 16
#define NN 2048
#define MM 2048
#define DD 128

// ---------------- scratch (__device__ globals: allocation-free rule) --------
__device__ __align__(16) float g_Qsq[BB * NN];
__device__ __align__(16) float g_Ksq[BB * MM];
__device__ __align__(16) __half g_Qh[(size_t)BB * NN * DD];
__device__ __align__(16) __half g_KTh[(size_t)BB * MM * DD];   // [b, m, d]

// ---------------- helpers ---------------------------------------------------
__device__ __forceinline__ uint32_t smem_u32(const void* p) {
    uint32_t a;
    asm("{ .reg .u64 t; cvta.to.shared.u64 t, %1; cvt.u32.u64 %0, t; }"
        : "=r"(a) : "l"(p));
    return a;
}
__device__ __forceinline__ void ldsm4(uint32_t* r, uint32_t addr) {
    asm volatile("ldmatrix.sync.aligned.m8n8.x4.shared.b16 {%0,%1,%2,%3}, [%4];"
                 : "=r"(r[0]), "=r"(r[1]), "=r"(r[2]), "=r"(r[3]) : "r"(addr));
}
__device__ __forceinline__ void mma16816(float* c, const uint32_t* a,
                                         const uint32_t* b) {
    asm volatile(
        "mma.sync.aligned.m16n8k16.row.col.f32.f16.f16.f32 "
        "{%0,%1,%2,%3}, {%4,%5,%6,%7}, {%8,%9}, {%0,%1,%2,%3};"
        : "+f"(c[0]), "+f"(c[1]), "+f"(c[2]), "+f"(c[3])
        : "r"(a[0]), "r"(a[1]), "r"(a[2]), "r"(a[3]), "r"(b[0]), "r"(b[1]));
}

// ---------------------------------------------------------------------------
// Prepass 1: Q[b,n,d] -> fp16 (row-major) + ||q||^2. One warp per row.
// ---------------------------------------------------------------------------
__global__ void qprep(const float* __restrict__ Q) {
    int row  = blockIdx.x * 8 + (threadIdx.x >> 5);
    int lane = threadIdx.x & 31;
    float4 v = reinterpret_cast<const float4*>(Q + (size_t)row * DD)[lane];
    float s = v.x * v.x + v.y * v.y + v.z * v.z + v.w * v.w;
    __half2 p0 = __floats2half2_rn(v.x, v.y);
    __half2 p1 = __floats2half2_rn(v.z, v.w);
    uint2 pk = make_uint2(*reinterpret_cast<uint32_t*>(&p0),
                          *reinterpret_cast<uint32_t*>(&p1));
    reinterpret_cast<uint2*>(g_Qh + (size_t)row * DD)[lane] = pk;
#pragma unroll
    for (int o = 16; o > 0; o >>= 1) s += __shfl_xor_sync(0xffffffffu, s, o);
    if (lane == 0) g_Qsq[row] = s;
}

// ---------------------------------------------------------------------------
// Prepass 2: KV[b,d,m] -> transpose to fp16 [b,m,d] + ||k||^2.
// ---------------------------------------------------------------------------
__global__ void kvprep(const float* __restrict__ KV) {
    __shared__ float s[128][33];
    __shared__ float csq[256];
    int b  = blockIdx.y;
    int m0 = blockIdx.x * 32;
    int t  = threadIdx.x;
    int mi = t & 31, dg = t >> 5;
    const float* base = KV + (size_t)b * DD * MM + m0;
    float acc = 0.f;
#pragma unroll
    for (int i = 0; i < 16; i++) {
        int d = i * 8 + dg;
        float v = base[(size_t)d * MM + mi];
        s[d][mi] = v;
        acc = fmaf(v, v, acc);
    }
    csq[t] = acc;
    __syncthreads();
    if (t < 32) {
        float a2 = 0.f;
#pragma unroll
        for (int j = 0; j < 8; j++) a2 += csq[t + j * 32];
        g_Ksq[(size_t)b * MM + m0 + t] = a2;
    }
#pragma unroll
    for (int it = 0; it < 2; it++) {
        int idx = it * 256 + t;
        int m = idx >> 4, kc = idx & 15, d0 = kc * 8;
        uint32_t p[4];
#pragma unroll
        for (int j = 0; j < 4; j++) {
            __half2 h = __floats2half2_rn(s[d0 + 2 * j][m], s[d0 + 2 * j + 1][m]);
            p[j] = *reinterpret_cast<uint32_t*>(&h);
        }
        *reinterpret_cast<uint4*>(g_KTh + ((size_t)b * MM + m0 + m) * DD + d0) =
            make_uint4(p[0], p[1], p[2], p[3]);
    }
}

// ---------------------------------------------------------------------------
// Main kernel: 128(n) x 128(m) tile per CTA via ldmatrix + mma.sync fp16,
// single pass, fp32 accumulate, fused exp epilogue.
// Smem tiles: 128 rows x 256B pitch; 16B chunks swizzled by (kc ^ (row & 7)).
// ---------------------------------------------------------------------------
#define SM_A 0
#define SM_B 32768
#define SMEM_TOTAL 65536

__global__ void __launch_bounds__(256, 2)
gauss_mma(const float* __restrict__ LS, float* __restrict__ OUT) {
    extern __shared__ char smem[];
    const uint32_t sb = smem_u32(smem);
    const int t = threadIdx.x, wid = t >> 5, lane = t & 31;
    const int b = blockIdx.z, n0 = blockIdx.y * 128, m0 = blockIdx.x * 128;

    // ---- bulk load the 2 operand tiles into swizzled smem ----
    {
        const __half* sA = g_Qh + ((size_t)b * NN + n0) * DD;
#pragma unroll
        for (int i = 0; i < 8; i++) {
            int idx = i * 256 + t;
            int row = idx >> 4, kc = idx & 15;
            uint4 v = *reinterpret_cast<const uint4*>(sA + (size_t)row * DD + kc * 8);
            *reinterpret_cast<uint4*>(
                smem + SM_A + row * 256 + ((kc ^ (row & 7)) << 4)) = v;
        }
        const __half* sB = g_KTh + ((size_t)b * MM + m0) * DD;
#pragma unroll
        for (int i = 0; i < 8; i++) {
            int idx = i * 256 + t;
            int row = idx >> 4, kc = idx & 15;
            uint4 v = *reinterpret_cast<const uint4*>(sB + (size_t)row * DD + kc * 8);
            *reinterpret_cast<uint4*>(
                smem + SM_B + row * 256 + ((kc ^ (row & 7)) << 4)) = v;
        }
    }
    __syncthreads();

    // ---- fragment addressing ----
    const int warp_r = wid & 1;        // 0..1 -> 64 out-rows each
    const int warp_c = wid >> 1;       // 0..3 -> 32 out-cols each
    const int rmask = lane & 7;

    // A (Q): mat = lane>>3; row = base + (lane&7) + (mat&1)*8; kchunk cA = mat>>1
    const int cA = lane >> 4;
    uint32_t arow_base[4];
#pragma unroll
    for (int rt = 0; rt < 4; rt++)
        arow_base[rt] = (uint32_t)((warp_r * 64 + rt * 16 + (lane & 7) +
                                    (((lane >> 3) & 1) << 3)) * 256);
    // B (KT): mat = lane>>3; row = base + (lane&7) + (mat>>1)*8; kchunk cB = mat&1
    const int cB = (lane >> 3) & 1;
    uint32_t brow_base[2];
#pragma unroll
    for (int p = 0; p < 2; p++)
        brow_base[p] = (uint32_t)((warp_c * 32 + p * 16 + (lane & 7) +
                                   ((lane >> 4) << 3)) * 256);

    float acc[4][4][4];
#pragma unroll
    for (int rt = 0; rt < 4; rt++)
#pragma unroll
        for (int ct = 0; ct < 4; ct++)
#pragma unroll
            for (int j = 0; j < 4; j++) acc[rt][ct][j] = 0.f;

    // ---- main MMA loop: 8 k-steps, single fp16 pass ----
#pragma unroll
    for (int ks = 0; ks < 8; ks++) {
        uint32_t a[4][4], bf[2][4];
        uint32_t aswz = (uint32_t)((((ks << 1) + cA) ^ rmask) << 4);
#pragma unroll
        for (int rt = 0; rt < 4; rt++)
            ldsm4(a[rt], sb + SM_A + arow_base[rt] + aswz);
        uint32_t bswz = (uint32_t)((((ks << 1) + cB) ^ rmask) << 4);
#pragma unroll
        for (int p = 0; p < 2; p++)
            ldsm4(bf[p], sb + SM_B + brow_base[p] + bswz);

#pragma unroll
        for (int rt = 0; rt < 4; rt++)
#pragma unroll
            for (int ct = 0; ct < 4; ct++)
                mma16816(acc[rt][ct], a[rt], bf[ct >> 1] + 2 * (ct & 1));
    }

    // ---- fused Gaussian epilogue ----
    const float cc  = -0.5f * __expf(-2.0f * LS[0]);
    const float m2c = -2.0f * cc;

    const int r_base = n0 + warp_r * 64;
    const int c_base = m0 + warp_c * 32;
    float cq[4][2], ck[4][2];
#pragma unroll
    for (int rt = 0; rt < 4; rt++)
#pragma unroll
        for (int h = 0; h < 2; h++)
            cq[rt][h] = cc * __ldg(&g_Qsq[(size_t)b * NN + r_base + rt * 16 +
                                          (lane >> 2) + h * 8]);
#pragma unroll
    for (int ct = 0; ct < 4; ct++)
#pragma unroll
        for (int j = 0; j < 2; j++)
            ck[ct][j] = cc * __ldg(&g_Ksq[(size_t)b * MM + c_base + ct * 8 +
                                          2 * (lane & 3) + j]);

#pragma unroll
    for (int rt = 0; rt < 4; rt++) {
#pragma unroll
        for (int ct = 0; ct < 4; ct++) {
#pragma unroll
            for (int h = 0; h < 2; h++) {
                int row = r_base + rt * 16 + (lane >> 2) + h * 8;
                int col = c_base + ct * 8 + 2 * (lane & 3);
                float2 o;
                o.x = __expf(fmaf(m2c, acc[rt][ct][2 * h + 0], cq[rt][h] + ck[ct][0]));
                o.y = __expf(fmaf(m2c, acc[rt][ct][2 * h + 1], cq[rt][h] + ck[ct][1]));
                *reinterpret_cast<float2*>(
                    OUT + ((size_t)b * NN + row) * MM + col) = o;
            }
        }
    }
}

// ---------------------------------------------------------------------------
extern "C" void kernel_launch(void* const* d_in, const int* in_sizes, int n_in,
                              void* d_out, int out_size) {
    const float* Q  = (const float*)d_in[0];
    const float* KV = (const float*)d_in[1];
    const float* LS = (const float*)d_in[2];
    float* OUT = (float*)d_out;

    cudaFuncSetAttribute(gauss_mma, cudaFuncAttributeMaxDynamicSharedMemorySize,
                         SMEM_TOTAL);

    qprep<<<BB * NN / 8, 256>>>(Q);
    kvprep<<<dim3(MM / 32, BB), 256>>>(KV);

    dim3 grid(MM / 128, NN / 128, BB);
    gauss_mma<<<grid, 256, SMEM_TOTAL>>>(LS, OUT);
}

// round 6
// speedup vs baseline: 4.3374x; 1.0431x over previous
#include <cuda_runtime.h>
#include <cuda_fp16.h>
#include <cstdint>

#define BB 16
#define NN 2048
#define MM 2048
#define DD 128

// ---------------- scratch (__device__ globals: allocation-free rule) --------
__device__ __align__(16) float g_Qsq[BB * NN];
__device__ __align__(16) float g_Ksq[BB * MM];
__device__ __align__(16) uint8_t g_Q8[(size_t)BB * NN * DD];    // e4m3 [b,n,d]
__device__ __align__(16) uint8_t g_KT8[(size_t)BB * MM * DD];   // e4m3 [b,m,d]

// ---------------- helpers ---------------------------------------------------
__device__ __forceinline__ uint32_t smem_u32(const void* p) {
    uint32_t a;
    asm("{ .reg .u64 t; cvta.to.shared.u64 t, %1; cvt.u32.u64 %0, t; }"
        : "=r"(a) : "l"(p));
    return a;
}
__device__ __forceinline__ uint16_t f2_e4m3x2(float hi, float lo) {
    // packs: low byte = lo, high byte = hi
    uint16_t r;
    asm("cvt.rn.satfinite.e4m3x2.f32 %0, %1, %2;" : "=h"(r) : "f"(hi), "f"(lo));
    return r;
}
__device__ __forceinline__ void ldsm4(uint32_t* r, uint32_t addr) {
    asm volatile("ldmatrix.sync.aligned.m8n8.x4.shared.b16 {%0,%1,%2,%3}, [%4];"
                 : "=r"(r[0]), "=r"(r[1]), "=r"(r[2]), "=r"(r[3]) : "r"(addr));
}
__device__ __forceinline__ void mma_fp8(float* c, const uint32_t* a,
                                        const uint32_t* b) {
    asm volatile(
        "mma.sync.aligned.m16n8k32.row.col.f32.e4m3.e4m3.f32 "
        "{%0,%1,%2,%3}, {%4,%5,%6,%7}, {%8,%9}, {%0,%1,%2,%3};"
        : "+f"(c[0]), "+f"(c[1]), "+f"(c[2]), "+f"(c[3])
        : "r"(a[0]), "r"(a[1]), "r"(a[2]), "r"(a[3]), "r"(b[0]), "r"(b[1]));
}

// ---------------------------------------------------------------------------
// Prepass 1: Q[b,n,d] -> e4m3 (row-major) + ||q||^2. One warp per row.
// ---------------------------------------------------------------------------
__global__ void qprep(const float* __restrict__ Q) {
    int row  = blockIdx.x * 8 + (threadIdx.x >> 5);
    int lane = threadIdx.x & 31;
    float4 v = reinterpret_cast<const float4*>(Q + (size_t)row * DD)[lane];
    float s = v.x * v.x + v.y * v.y + v.z * v.z + v.w * v.w;
    uint32_t pk = (uint32_t)f2_e4m3x2(v.y, v.x)
                | ((uint32_t)f2_e4m3x2(v.w, v.z) << 16);
    reinterpret_cast<uint32_t*>(g_Q8 + (size_t)row * DD)[lane] = pk;
#pragma unroll
    for (int o = 16; o > 0; o >>= 1) s += __shfl_xor_sync(0xffffffffu, s, o);
    if (lane == 0) g_Qsq[row] = s;
}

// ---------------------------------------------------------------------------
// Prepass 2: KV[b,d,m] -> transpose to e4m3 [b,m,d] + ||k||^2.
// ---------------------------------------------------------------------------
__global__ void kvprep(const float* __restrict__ KV) {
    __shared__ float s[128][33];
    __shared__ float csq[256];
    int b  = blockIdx.y;
    int m0 = blockIdx.x * 32;
    int t  = threadIdx.x;
    int mi = t & 31, dg = t >> 5;
    const float* base = KV + (size_t)b * DD * MM + m0;
    float acc = 0.f;
#pragma unroll
    for (int i = 0; i < 16; i++) {
        int d = i * 8 + dg;
        float v = base[(size_t)d * MM + mi];
        s[d][mi] = v;
        acc = fmaf(v, v, acc);
    }
    csq[t] = acc;
    __syncthreads();
    if (t < 32) {
        float a2 = 0.f;
#pragma unroll
        for (int j = 0; j < 8; j++) a2 += csq[t + j * 32];
        g_Ksq[(size_t)b * MM + m0 + t] = a2;
    }
#pragma unroll
    for (int it = 0; it < 2; it++) {
        int idx = it * 256 + t;
        int m = idx >> 4, kc = idx & 15, d0 = kc * 8;
        uint32_t lo = (uint32_t)f2_e4m3x2(s[d0 + 1][m], s[d0 + 0][m])
                    | ((uint32_t)f2_e4m3x2(s[d0 + 3][m], s[d0 + 2][m]) << 16);
        uint32_t hi = (uint32_t)f2_e4m3x2(s[d0 + 5][m], s[d0 + 4][m])
                    | ((uint32_t)f2_e4m3x2(s[d0 + 7][m], s[d0 + 6][m]) << 16);
        *reinterpret_cast<uint2*>(g_KT8 + ((size_t)b * MM + m0 + m) * DD + d0) =
            make_uint2(lo, hi);
    }
}

// ---------------------------------------------------------------------------
// Main kernel: 128(n) x 128(m) tile per CTA via ldmatrix + mma.sync e4m3,
// single pass, fp32 accumulate, fused exp epilogue.
// Smem tiles: 128 rows x 128B pitch; 16B chunks swizzled by (kc ^ (row & 7)).
// ---------------------------------------------------------------------------
#define SM_A 0
#define SM_B 16384
#define SMEM_TOTAL 32768

__global__ void __launch_bounds__(256, 2)
gauss_mma(const float* __restrict__ LS, float* __restrict__ OUT) {
    extern __shared__ char smem[];
    const uint32_t sb = smem_u32(smem);
    const int t = threadIdx.x, wid = t >> 5, lane = t & 31;
    const int b = blockIdx.z, n0 = blockIdx.y * 128, m0 = blockIdx.x * 128;

    // ---- bulk load the 2 operand tiles into swizzled smem ----
    {
        const uint8_t* sA = g_Q8 + ((size_t)b * NN + n0) * DD;
#pragma unroll
        for (int i = 0; i < 4; i++) {
            int idx = i * 256 + t;
            int row = idx >> 3, kc = idx & 7;
            uint4 v = *reinterpret_cast<const uint4*>(sA + (size_t)row * DD + kc * 16);
            *reinterpret_cast<uint4*>(
                smem + SM_A + row * 128 + ((kc ^ (row & 7)) << 4)) = v;
        }
        const uint8_t* sB = g_KT8 + ((size_t)b * MM + m0) * DD;
#pragma unroll
        for (int i = 0; i < 4; i++) {
            int idx = i * 256 + t;
            int row = idx >> 3, kc = idx & 7;
            uint4 v = *reinterpret_cast<const uint4*>(sB + (size_t)row * DD + kc * 16);
            *reinterpret_cast<uint4*>(
                smem + SM_B + row * 128 + ((kc ^ (row & 7)) << 4)) = v;
        }
    }
    __syncthreads();

    // ---- fragment addressing ----
    const int warp_r = wid & 1;        // 0..1 -> 64 out-rows each
    const int warp_c = wid >> 1;       // 0..3 -> 32 out-cols each
    const int rmask = lane & 7;

    // A: lanes 0-7 m0(rows 0-7, chunk kc), 8-15 m1(rows 8-15, kc),
    //    16-23 m2(rows 0-7, kc+1), 24-31 m3(rows 8-15, kc+1)
    //    -> a0..a3 match e4m3 m16n8k32 A fragment (4-byte k-groups).
    const int cA = lane >> 4;                 // chunk offset within pair
    uint32_t arow_base[4];
#pragma unroll
    for (int rt = 0; rt < 4; rt++)
        arow_base[rt] = (uint32_t)((warp_r * 64 + rt * 16 + (lane & 7) +
                                    (((lane >> 3) & 1) << 3)) * 128);
    // B: lanes 0-7 m0(cols 0-7, chunk kc), 8-15 m1(cols 0-7, kc+1),
    //    16-23 m2(cols 8-15, kc), 24-31 m3(cols 8-15, kc+1)
    const int cB = (lane >> 3) & 1;
    uint32_t bcol_base[2];
#pragma unroll
    for (int p = 0; p < 2; p++)
        bcol_base[p] = (uint32_t)((warp_c * 32 + p * 16 + (lane & 7) +
                                   ((lane >> 4) << 3)) * 128);

    float acc[4][4][4];
#pragma unroll
    for (int rt = 0; rt < 4; rt++)
#pragma unroll
        for (int ct = 0; ct < 4; ct++)
#pragma unroll
            for (int j = 0; j < 4; j++) acc[rt][ct][j] = 0.f;

    // ---- main MMA loop: 4 k-steps (k32 each), single e4m3 pass ----
#pragma unroll
    for (int ks = 0; ks < 4; ks++) {
        uint32_t a[4][4], bf[2][4];
        uint32_t aswz = (uint32_t)((((ks << 1) + cA) ^ rmask) << 4);
#pragma unroll
        for (int rt = 0; rt < 4; rt++)
            ldsm4(a[rt], sb + SM_A + arow_base[rt] + aswz);
        uint32_t bswz = (uint32_t)((((ks << 1) + cB) ^ rmask) << 4);
#pragma unroll
        for (int p = 0; p < 2; p++)
            ldsm4(bf[p], sb + SM_B + bcol_base[p] + bswz);

#pragma unroll
        for (int rt = 0; rt < 4; rt++)
#pragma unroll
            for (int ct = 0; ct < 4; ct++)
                mma_fp8(acc[rt][ct], a[rt], bf[ct >> 1] + 2 * (ct & 1));
    }

    // ---- fused Gaussian epilogue ----
    const float cc  = -0.5f * __expf(-2.0f * LS[0]);
    const float m2c = -2.0f * cc;

    const int r_base = n0 + warp_r * 64;
    const int c_base = m0 + warp_c * 32;
    float cq[4][2], ck[4][2];
#pragma unroll
    for (int rt = 0; rt < 4; rt++)
#pragma unroll
        for (int h = 0; h < 2; h++)
            cq[rt][h] = cc * __ldg(&g_Qsq[(size_t)b * NN + r_base + rt * 16 +
                                          (lane >> 2) + h * 8]);
#pragma unroll
    for (int ct = 0; ct < 4; ct++)
#pragma unroll
        for (int j = 0; j < 2; j++)
            ck[ct][j] = cc * __ldg(&g_Ksq[(size_t)b * MM + c_base + ct * 8 +
                                          2 * (lane & 3) + j]);

#pragma unroll
    for (int rt = 0; rt < 4; rt++) {
#pragma unroll
        for (int ct = 0; ct < 4; ct++) {
#pragma unroll
            for (int h = 0; h < 2; h++) {
                int row = r_base + rt * 16 + (lane >> 2) + h * 8;
                int col = c_base + ct * 8 + 2 * (lane & 3);
                float2 o;
                o.x = __expf(fmaf(m2c, acc[rt][ct][2 * h + 0], cq[rt][h] + ck[ct][0]));
                o.y = __expf(fmaf(m2c, acc[rt][ct][2 * h + 1], cq[rt][h] + ck[ct][1]));
                *reinterpret_cast<float2*>(
                    OUT + ((size_t)b * NN + row) * MM + col) = o;
            }
        }
    }
}

// ---------------------------------------------------------------------------
extern "C" void kernel_launch(void* const* d_in, const int* in_sizes, int n_in,
                              void* d_out, int out_size) {
    const float* Q  = (const float*)d_in[0];
    const float* KV = (const float*)d_in[1];
    const float* LS = (const float*)d_in[2];
    float* OUT = (float*)d_out;

    cudaFuncSetAttribute(gauss_mma, cudaFuncAttributeMaxDynamicSharedMemorySize,
                         SMEM_TOTAL);

    qprep<<<BB * NN / 8, 256>>>(Q);
    kvprep<<<dim3(MM / 32, BB), 256>>>(KV);

    dim3 grid(MM / 128, NN / 128, BB);
    gauss_mma<<<grid, 256, SMEM_TOTAL>>>(LS, OUT);
}

// round 8
// speedup vs baseline: 4.8058x; 1.1080x over previous
#include <cuda_runtime.h>
#include <cuda_fp16.h>
#include <cstdint>

#define BB 16
#define NN 2048
#define MM 2048
#define DD 128

// ---------------- scratch (__device__ globals: allocation-free rule) --------
__device__ __align__(16) float g_Qsq[BB * NN];
__device__ __align__(16) float g_Ksq[BB * MM];
__device__ __align__(16) uint8_t g_Q8[(size_t)BB * NN * DD];    // e4m3 [b,n,d]
__device__ __align__(16) uint8_t g_KT8[(size_t)BB * MM * DD];   // e4m3 [b,m,d]

// ---------------- helpers ---------------------------------------------------
__device__ __forceinline__ uint32_t smem_u32(const void* p) {
    uint32_t a;
    asm("{ .reg .u64 t; cvta.to.shared.u64 t, %1; cvt.u32.u64 %0, t; }"
        : "=r"(a) : "l"(p));
    return a;
}
__device__ __forceinline__ uint16_t f2_e4m3x2(float hi, float lo) {
    uint16_t r;
    asm("cvt.rn.satfinite.e4m3x2.f32 %0, %1, %2;" : "=h"(r) : "f"(hi), "f"(lo));
    return r;
}
__device__ __forceinline__ void ldsm4(uint32_t* r, uint32_t addr) {
    asm volatile("ldmatrix.sync.aligned.m8n8.x4.shared.b16 {%0,%1,%2,%3}, [%4];"
                 : "=r"(r[0]), "=r"(r[1]), "=r"(r[2]), "=r"(r[3]) : "r"(addr));
}
__device__ __forceinline__ void mma_fp8(float* c, const uint32_t* a,
                                        const uint32_t* b) {
    asm volatile(
        "mma.sync.aligned.m16n8k32.row.col.f32.e4m3.e4m3.f32 "
        "{%0,%1,%2,%3}, {%4,%5,%6,%7}, {%8,%9}, {%0,%1,%2,%3};"
        : "+f"(c[0]), "+f"(c[1]), "+f"(c[2]), "+f"(c[3])
        : "r"(a[0]), "r"(a[1]), "r"(a[2]), "r"(a[3]), "r"(b[0]), "r"(b[1]));
}
__device__ __forceinline__ void stcs2(float* p, float x, float y) {
    asm volatile("st.global.cs.v2.f32 [%0], {%1, %2};" :: "l"(p), "f"(x), "f"(y)
                 : "memory");
}

// ---------------------------------------------------------------------------
// Merged prepass. Blocks [0, 4096): Q -> e4m3 + ||q||^2 (one warp per row).
// Blocks [4096, 5120): KV -> transpose to e4m3 [b,m,d] + ||k||^2.
// ---------------------------------------------------------------------------
__global__ void prep(const float* __restrict__ Q, const float* __restrict__ KV) {
    __shared__ float s[128][33];
    __shared__ float csq[256];
    const int t = threadIdx.x;

    if (blockIdx.x < 4096) {
        int row  = blockIdx.x * 8 + (t >> 5);
        int lane = t & 31;
        float4 v = reinterpret_cast<const float4*>(Q + (size_t)row * DD)[lane];
        float sum = v.x * v.x + v.y * v.y + v.z * v.z + v.w * v.w;
        uint32_t pk = (uint32_t)f2_e4m3x2(v.y, v.x)
                    | ((uint32_t)f2_e4m3x2(v.w, v.z) << 16);
        reinterpret_cast<uint32_t*>(g_Q8 + (size_t)row * DD)[lane] = pk;
#pragma unroll
        for (int o = 16; o > 0; o >>= 1) sum += __shfl_xor_sync(0xffffffffu, sum, o);
        if (lane == 0) g_Qsq[row] = sum;
        return;
    }

    const int bid = blockIdx.x - 4096;
    const int b  = bid >> 6;
    const int m0 = (bid & 63) * 32;
    const int mi = t & 31, dg = t >> 5;
    const float* base = KV + (size_t)b * DD * MM + m0;
    float acc = 0.f;
#pragma unroll
    for (int i = 0; i < 16; i++) {
        int d = i * 8 + dg;
        float v = base[(size_t)d * MM + mi];
        s[d][mi] = v;
        acc = fmaf(v, v, acc);
    }
    csq[t] = acc;
    __syncthreads();
    if (t < 32) {
        float a2 = 0.f;
#pragma unroll
        for (int j = 0; j < 8; j++) a2 += csq[t + j * 32];
        g_Ksq[(size_t)b * MM + m0 + t] = a2;
    }
#pragma unroll
    for (int it = 0; it < 2; it++) {
        int idx = it * 256 + t;
        int m = idx >> 4, kc = idx & 15, d0 = kc * 8;
        uint32_t lo = (uint32_t)f2_e4m3x2(s[d0 + 1][m], s[d0 + 0][m])
                    | ((uint32_t)f2_e4m3x2(s[d0 + 3][m], s[d0 + 2][m]) << 16);
        uint32_t hi = (uint32_t)f2_e4m3x2(s[d0 + 5][m], s[d0 + 4][m])
                    | ((uint32_t)f2_e4m3x2(s[d0 + 7][m], s[d0 + 6][m]) << 16);
        *reinterpret_cast<uint2*>(g_KT8 + ((size_t)b * MM + m0 + m) * DD + d0) =
            make_uint2(lo, hi);
    }
}

// ---------------------------------------------------------------------------
// Main kernel: 128(n) x 128(m) tile per CTA via ldmatrix + mma.sync e4m3,
// single pass, fp32 accumulate, fused exp epilogue, streaming stores.
// Smem tiles: 128 rows x 128B pitch; 16B chunks swizzled by (kc ^ (row & 7)).
// ---------------------------------------------------------------------------
#define SM_A 0
#define SM_B 16384
#define SMEM_TOTAL 32768

__global__ void __launch_bounds__(256, 2)
gauss_mma(const float* __restrict__ LS, float* __restrict__ OUT) {
    extern __shared__ char smem[];
    const uint32_t sb = smem_u32(smem);
    const int t = threadIdx.x, wid = t >> 5, lane = t & 31;
    const int b = blockIdx.z, n0 = blockIdx.y * 128, m0 = blockIdx.x * 128;

    // ---- bulk load the 2 operand tiles into swizzled smem ----
    {
        const uint8_t* sA = g_Q8 + ((size_t)b * NN + n0) * DD;
#pragma unroll
        for (int i = 0; i < 4; i++) {
            int idx = i * 256 + t;
            int row = idx >> 3, kc = idx & 7;
            uint4 v = *reinterpret_cast<const uint4*>(sA + (size_t)row * DD + kc * 16);
            *reinterpret_cast<uint4*>(
                smem + SM_A + row * 128 + ((kc ^ (row & 7)) << 4)) = v;
        }
        const uint8_t* sB = g_KT8 + ((size_t)b * MM + m0) * DD;
#pragma unroll
        for (int i = 0; i < 4; i++) {
            int idx = i * 256 + t;
            int row = idx >> 3, kc = idx & 7;
            uint4 v = *reinterpret_cast<const uint4*>(sB + (size_t)row * DD + kc * 16);
            *reinterpret_cast<uint4*>(
                smem + SM_B + row * 128 + ((kc ^ (row & 7)) << 4)) = v;
        }
    }
    __syncthreads();

    // ---- fragment addressing ----
    const int warp_r = wid & 1;        // 0..1 -> 64 out-rows each
    const int warp_c = wid >> 1;       // 0..3 -> 32 out-cols each
    const int rmask = lane & 7;

    const int cA = lane >> 4;
    uint32_t arow_base[4];
#pragma unroll
    for (int rt = 0; rt < 4; rt++)
        arow_base[rt] = (uint32_t)((warp_r * 64 + rt * 16 + (lane & 7) +
                                    (((lane >> 3) & 1) << 3)) * 128);
    const int cB = (lane >> 3) & 1;
    uint32_t bcol_base[2];
#pragma unroll
    for (int p = 0; p < 2; p++)
        bcol_base[p] = (uint32_t)((warp_c * 32 + p * 16 + (lane & 7) +
                                   ((lane >> 4) << 3)) * 128);

    float acc[4][4][4];
#pragma unroll
    for (int rt = 0; rt < 4; rt++)
#pragma unroll
        for (int ct = 0; ct < 4; ct++)
#pragma unroll
            for (int j = 0; j < 4; j++) acc[rt][ct][j] = 0.f;

    // ---- main MMA loop: 4 k-steps (k32 each), single e4m3 pass ----
#pragma unroll
    for (int ks = 0; ks < 4; ks++) {
        uint32_t a[4][4], bf[2][4];
        uint32_t aswz = (uint32_t)((((ks << 1) + cA) ^ rmask) << 4);
#pragma unroll
        for (int rt = 0; rt < 4; rt++)
            ldsm4(a[rt], sb + SM_A + arow_base[rt] + aswz);
        uint32_t bswz = (uint32_t)((((ks << 1) + cB) ^ rmask) << 4);
#pragma unroll
        for (int p = 0; p < 2; p++)
            ldsm4(bf[p], sb + SM_B + bcol_base[p] + bswz);

#pragma unroll
        for (int rt = 0; rt < 4; rt++)
#pragma unroll
            for (int ct = 0; ct < 4; ct++)
                mma_fp8(acc[rt][ct], a[rt], bf[ct >> 1] + 2 * (ct & 1));
    }

    // ---- fused Gaussian epilogue ----
    const float cc  = -0.5f * __expf(-2.0f * LS[0]);
    const float m2c = -2.0f * cc;

    const int r_base = n0 + warp_r * 64;
    const int c_base = m0 + warp_c * 32;
    float cq[4][2], ck[4][2];
#pragma unroll
    for (int rt = 0; rt < 4; rt++)
#pragma unroll
        for (int h = 0; h < 2; h++)
            cq[rt][h] = cc * __ldg(&g_Qsq[(size_t)b * NN + r_base + rt * 16 +
                                          (lane >> 2) + h * 8]);
#pragma unroll
    for (int ct = 0; ct < 4; ct++)
#pragma unroll
        for (int j = 0; j < 2; j++)
            ck[ct][j] = cc * __ldg(&g_Ksq[(size_t)b * MM + c_base + ct * 8 +
                                          2 * (lane & 3) + j]);

#pragma unroll
    for (int rt = 0; rt < 4; rt++) {
#pragma unroll
        for (int ct = 0; ct < 4; ct++) {
#pragma unroll
            for (int h = 0; h < 2; h++) {
                int row = r_base + rt * 16 + (lane >> 2) + h * 8;
                int col = c_base + ct * 8 + 2 * (lane & 3);
                float ox = __expf(fmaf(m2c, acc[rt][ct][2 * h + 0], cq[rt][h] + ck[ct][0]));
                float oy = __expf(fmaf(m2c, acc[rt][ct][2 * h + 1], cq[rt][h] + ck[ct][1]));
                stcs2(OUT + ((size_t)b * NN + row) * MM + col, ox, oy);
            }
        }
    }
}

// ---------------------------------------------------------------------------
extern "C" void kernel_launch(void* const* d_in, const int* in_sizes, int n_in,
                              void* d_out, int out_size) {
    const float* Q  = (const float*)d_in[0];
    const float* KV = (const float*)d_in[1];
    const float* LS = (const float*)d_in[2];
    float* OUT = (float*)d_out;

    cudaFuncSetAttribute(gauss_mma, cudaFuncAttributeMaxDynamicSharedMemorySize,
                         SMEM_TOTAL);

    prep<<<4096 + 1024, 256>>>(Q, KV);

    dim3 grid(MM / 128, NN / 128, BB);
    gauss_mma<<<grid, 256, SMEM_TOTAL>>>(LS, OUT);
}